// round 2
// baseline (speedup 1.0000x reference)
#include <cuda_runtime.h>

#define NBATCH 4
#define HH 128
#define WW 128
#define TT 32

// ---------------- tables + scratch (device globals: no runtime allocation) ----
static __device__ float g_srm0[32];
static __device__ float g_refc1[32];
static __device__ float g_refc2[32];

static __device__ float g_psp0 [(size_t)NBATCH * 2  * HH * WW * TT]; //  16 MB
static __device__ float g_psps1[(size_t)NBATCH * 16 * HH * WW * TT]; // 128 MB
static __device__ float g_p2   [(size_t)NBATCH * 16 * HH * WW * TT]; // 128 MB
static __device__ float g_psps2[(size_t)NBATCH * 16 * HH * WW * TT]; // 128 MB

#define Q1F  0.60653065971263342f  /* exp(-1/2)  */
#define Q2F  0.77880078307140487f  /* exp(-1/4)  */
#define CS1F 1.3591409142295226f   /* e/2 : srm1[k] = CS1*k*Q1^k */
#define CS2F 0.67957045711476131f  /* e/4 : srm2[k] = CS2*k*Q2^k */

// ---------------- init: alpha-kernel tables (match reference truncation) -----
__global__ void k_init() {
    int t = threadIdx.x;
    if (t < 32) {
        double td = (double)t;
        double v0 = td * exp(1.0 - td);                    // srm0 (tau=1), trunc@18
        g_srm0[t]  = (t < 18) ? (float)v0 : 0.0f;
        double r1 = -3.0 * td * exp(1.0 - td);             // refk layer1, trunc@19
        g_refc1[t] = (t < 19) ? (float)r1 : 0.0f;
        double r2 = -5.0 * (td * 0.5) * exp(1.0 - td * 0.5); // refk layer2, full 32
        g_refc2[t] = (float)r2;
    }
}

// ---------------- psp0: temporal filter of binary input ---------------------
__global__ void __launch_bounds__(256) k_psp0(const float* __restrict__ in) {
    int gid = blockIdx.x * blockDim.x + threadIdx.x;   // (n,c,h,w) : 131072
    const float4* src = (const float4*)(in + (size_t)gid * TT);
    float x[TT];
#pragma unroll
    for (int v = 0; v < 8; v++) {
        float4 f = src[v];
        x[4*v] = f.x; x[4*v+1] = f.y; x[4*v+2] = f.z; x[4*v+3] = f.w;
    }
    float s0[18];
#pragma unroll
    for (int k = 0; k < 18; k++) s0[k] = g_srm0[k];
    float y[TT];
#pragma unroll
    for (int t = 0; t < TT; t++) {
        float a = 0.f;
#pragma unroll
        for (int k = 1; k < 18; k++)
            if (k <= t) a += x[t - k] * s0[k];
        y[t] = a;
    }
    float4* dst = (float4*)(g_psp0 + (size_t)gid * TT);
#pragma unroll
    for (int v = 0; v < 8; v++)
        dst[v] = make_float4(y[4*v], y[4*v+1], y[4*v+2], y[4*v+3]);
}

// ---------------- fused: conv1 (3x3, 2->16) + spike1 + psp(s1,srm1) ---------
__global__ void __launch_bounds__(256) k_l1(const float* __restrict__ w1) {
    int gid = blockIdx.x * 256 + threadIdx.x;          // (n,co,h,w) : 2^20
    int w  = gid & 127;
    int h  = (gid >> 7) & 127;
    int co = (gid >> 14) & 15;
    int n  = gid >> 18;

    float wv[18];
#pragma unroll
    for (int i = 0; i < 18; i++) wv[i] = w1[co * 18 + i];

    float acc[TT];
#pragma unroll
    for (int t = 0; t < TT; t++) acc[t] = 0.f;

#pragma unroll
    for (int ci = 0; ci < 2; ci++)
#pragma unroll
        for (int ky = 0; ky < 3; ky++) {
            int ih = h + ky - 1;
            if ((unsigned)ih >= 128u) continue;
#pragma unroll
            for (int kx = 0; kx < 3; kx++) {
                int iw = w + kx - 1;
                if ((unsigned)iw >= 128u) continue;
                float wgt = wv[ci * 9 + ky * 3 + kx];
                const float4* p = (const float4*)(g_psp0 +
                    ((((size_t)n * 2 + ci) * 128 + ih) * 128 + iw) * TT);
#pragma unroll
                for (int v = 0; v < 8; v++) {
                    float4 f = p[v];
                    acc[4*v]   += f.x * wgt;
                    acc[4*v+1] += f.y * wgt;
                    acc[4*v+2] += f.z * wgt;
                    acc[4*v+3] += f.w * wgt;
                }
            }
        }

    // spike1 (theta=3, truncated refractory len 19, exact replay) + psp1 recurrence
    float rc[19];
#pragma unroll
    for (int d = 1; d < 19; d++) rc[d] = g_refc1[d];
    float r[TT];
#pragma unroll
    for (int t = 0; t < TT; t++) r[t] = 0.f;
    float A = 0.f, B = 0.f;
#pragma unroll
    for (int t = 0; t < TT; t++) {
        float u = acc[t] + r[t];
        bool sp = (u >= 3.0f);
        B = Q1F * (B + A);
        A = Q1F * A + (sp ? 1.0f : 0.0f);
        acc[t] = CS1F * B;                 // psp(s1) output, slot t consumed
        if (sp) {
#pragma unroll
            for (int d = 1; d < 19; d++)
                if (t + d < TT) r[t + d] += rc[d];
        }
    }

    float4* dst = (float4*)(g_psps1 + (size_t)gid * TT);
#pragma unroll
    for (int v = 0; v < 8; v++)
        dst[v] = make_float4(acc[4*v], acc[4*v+1], acc[4*v+2], acc[4*v+3]);
}

// ---------------- conv2 (3x3, 18->16), smem tiled, FMA-bound ----------------
// block = 16x16 pixels, one (n, t-chunk of 4); thread = 1 pixel x 16co x 4t
__global__ void __launch_bounds__(256, 2) k_conv2(const float* __restrict__ w2) {
    extern __shared__ float smem[];
    float* wT   = smem;          // [162][16]   co-contiguous
    float* tile = smem + 2592;   // [18][18][18][4]  (ci, yy, xx, tt)

    int tid = threadIdx.x;
    int x = tid & 15, y = tid >> 4;
    int w0 = blockIdx.x * 16, h0 = blockIdx.y * 16;
    int bz = blockIdx.z;
    int n = bz >> 3, t0 = (bz & 7) * 4;

    for (int i = tid; i < 2592; i += 256) {        // w2: [co][ci][ky][kx]
        int co = i / 162, tap = i - co * 162;
        wT[tap * 16 + co] = w2[i];
    }
    for (int i = tid; i < 5832; i += 256) {        // 18*18*18 float4 chunks
        int ci  = i / 324;
        int rem = i - ci * 324;
        int yy = rem / 18, xx = rem - yy * 18;
        int gh = h0 + yy - 1, gw = w0 + xx - 1;
        float4 v = make_float4(0.f, 0.f, 0.f, 0.f);
        if ((unsigned)gh < 128u && (unsigned)gw < 128u) {
            const float* srcp = (ci < 16)
                ? (g_psps1 + ((((size_t)n * 16 + ci)        * 128 + gh) * 128 + gw) * TT + t0)
                : (g_psp0  + ((((size_t)n * 2  + (ci - 16)) * 128 + gh) * 128 + gw) * TT + t0);
            v = *(const float4*)srcp;
        }
        *(float4*)&tile[(size_t)i * 4] = v;
    }
    __syncthreads();

    float acc[64];                                  // acc[co*4 + tt]
#pragma unroll
    for (int i = 0; i < 64; i++) acc[i] = 0.f;

    for (int ci = 0; ci < 18; ci++) {
#pragma unroll
        for (int ky = 0; ky < 3; ky++)
#pragma unroll
            for (int kx = 0; kx < 3; kx++) {
                float4 in4 = *(const float4*)&tile[(((ci * 18) + (y + ky)) * 18 + (x + kx)) * 4];
                int tap = ci * 9 + ky * 3 + kx;
#pragma unroll
                for (int cg = 0; cg < 4; cg++) {
                    float4 wq = *(const float4*)&wT[tap * 16 + cg * 4];
                    int b = cg * 16;
                    acc[b+0]  += in4.x * wq.x; acc[b+1]  += in4.y * wq.x;
                    acc[b+2]  += in4.z * wq.x; acc[b+3]  += in4.w * wq.x;
                    acc[b+4]  += in4.x * wq.y; acc[b+5]  += in4.y * wq.y;
                    acc[b+6]  += in4.z * wq.y; acc[b+7]  += in4.w * wq.y;
                    acc[b+8]  += in4.x * wq.z; acc[b+9]  += in4.y * wq.z;
                    acc[b+10] += in4.z * wq.z; acc[b+11] += in4.w * wq.z;
                    acc[b+12] += in4.x * wq.w; acc[b+13] += in4.y * wq.w;
                    acc[b+14] += in4.z * wq.w; acc[b+15] += in4.w * wq.w;
                }
            }
    }

    int gh = h0 + y, gw = w0 + x;
#pragma unroll
    for (int co = 0; co < 16; co++) {
        size_t o = ((((size_t)n * 16 + co) * 128 + gh) * 128 + gw) * TT + t0;
        *(float4*)&g_p2[o] = make_float4(acc[co*4], acc[co*4+1], acc[co*4+2], acc[co*4+3]);
    }
}

// ---------------- spike2 (theta=5) + psp(s2, srm2) --------------------------
__global__ void __launch_bounds__(256) k_spike2() {
    int gid = blockIdx.x * blockDim.x + threadIdx.x;   // 2^20 neurons
    float pv[TT];
    const float4* src = (const float4*)(g_p2 + (size_t)gid * TT);
#pragma unroll
    for (int v = 0; v < 8; v++) {
        float4 f = src[v];
        pv[4*v] = f.x; pv[4*v+1] = f.y; pv[4*v+2] = f.z; pv[4*v+3] = f.w;
    }
    float rc[32];
#pragma unroll
    for (int d = 1; d < 32; d++) rc[d] = g_refc2[d];
    float r[TT];
#pragma unroll
    for (int t = 0; t < TT; t++) r[t] = 0.f;
    float A = 0.f, B = 0.f;
#pragma unroll
    for (int t = 0; t < TT; t++) {
        float u = pv[t] + r[t];
        bool sp = (u >= 5.0f);
        B = Q2F * (B + A);
        A = Q2F * A + (sp ? 1.0f : 0.0f);
        pv[t] = CS2F * B;                  // psp(s2)
        if (sp) {
#pragma unroll
            for (int d = 1; d < 32; d++)
                if (t + d < TT) r[t + d] += rc[d];
        }
    }
    float4* dst = (float4*)(g_psps2 + (size_t)gid * TT);
#pragma unroll
    for (int v = 0; v < 8; v++)
        dst[v] = make_float4(pv[4*v], pv[4*v+1], pv[4*v+2], pv[4*v+3]);
}

// ---------------- conv3 (1x1, 18->32) ---------------------------------------
// thread = (pixel, 4t, 16-co half); lanes: t-chunks fastest -> coalesced IO
__global__ void __launch_bounds__(256) k_conv3(const float* __restrict__ w3,
                                               float* __restrict__ out) {
    __shared__ __align__(16) float wS[18 * 32];        // [ci][co]
    int tid = threadIdx.x;
    for (int i = tid; i < 576; i += 256) {             // w3: [co][ci]
        int co = i / 18, ci = i - co * 18;
        wS[ci * 32 + co] = w3[i];
    }
    __syncthreads();

    int gid = blockIdx.x * 256 + tid;                  // (n,h,w,tc) : 2^19
    int tc  = gid & 7;
    int pix = gid >> 3;
    int n   = pix >> 14;
    int hw  = pix & 16383;
    int t0  = tc * 4;
    int cob = blockIdx.y * 16;

    float acc[64];
#pragma unroll
    for (int i = 0; i < 64; i++) acc[i] = 0.f;

#pragma unroll
    for (int ci = 0; ci < 18; ci++) {
        const float* srcp = (ci < 16)
            ? (g_psps2 + (((size_t)n * 16 + ci)        * 16384 + hw) * TT + t0)
            : (g_psp0  + (((size_t)n * 2  + (ci - 16)) * 16384 + hw) * TT + t0);
        float4 in4 = *(const float4*)srcp;
#pragma unroll
        for (int cg = 0; cg < 4; cg++) {
            float4 wq = *(const float4*)&wS[ci * 32 + cob + cg * 4];
            int b = cg * 16;
            acc[b+0]  += in4.x * wq.x; acc[b+1]  += in4.y * wq.x;
            acc[b+2]  += in4.z * wq.x; acc[b+3]  += in4.w * wq.x;
            acc[b+4]  += in4.x * wq.y; acc[b+5]  += in4.y * wq.y;
            acc[b+6]  += in4.z * wq.y; acc[b+7]  += in4.w * wq.y;
            acc[b+8]  += in4.x * wq.z; acc[b+9]  += in4.y * wq.z;
            acc[b+10] += in4.z * wq.z; acc[b+11] += in4.w * wq.z;
            acc[b+12] += in4.x * wq.w; acc[b+13] += in4.y * wq.w;
            acc[b+14] += in4.z * wq.w; acc[b+15] += in4.w * wq.w;
        }
    }
#pragma unroll
    for (int co = 0; co < 16; co++) {
        size_t o = (((size_t)n * 32 + cob + co) * 16384 + hw) * TT + t0;
        *(float4*)&out[o] = make_float4(acc[co*4], acc[co*4+1], acc[co*4+2], acc[co*4+3]);
    }
}

// ---------------- launcher ---------------------------------------------------
extern "C" void kernel_launch(void* const* d_in, const int* in_sizes, int n_in,
                              void* d_out, int out_size) {
    const float* spikeIn = (const float*)d_in[0];
    const float* w1 = (const float*)d_in[1];
    const float* w2 = (const float*)d_in[2];
    const float* w3 = (const float*)d_in[3];
    float* out = (float*)d_out;

    const int conv2_smem = 25920 * 4;  // 103,680 B
    cudaFuncSetAttribute(k_conv2, cudaFuncAttributeMaxDynamicSharedMemorySize, conv2_smem);

    k_init<<<1, 32>>>();
    k_psp0<<<512, 256>>>(spikeIn);
    k_l1<<<4096, 256>>>(w1);
    dim3 g2(8, 8, 32);
    k_conv2<<<g2, 256, conv2_smem>>>(w2);
    k_spike2<<<4096, 256>>>();
    dim3 g3(2048, 2);
    k_conv3<<<g3, 256>>>(w3, out);
}

// round 5
// speedup vs baseline: 1.0781x; 1.0781x over previous
#include <cuda_runtime.h>

#define NBATCH 4
#define HH 128
#define WW 128
#define TT 32

typedef unsigned long long ull;

// ---------------- f32x2 packed-math helpers (sm_103a) -----------------------
__device__ __forceinline__ ull f2fma(ull a, ull b, ull c) {
    ull d;
    asm("fma.rn.f32x2 %0, %1, %2, %3;" : "=l"(d) : "l"(a), "l"(b), "l"(c));
    return d;
}
__device__ __forceinline__ ull f2pack(float lo, float hi) {
    ull r; asm("mov.b64 %0, {%1, %2};" : "=l"(r) : "f"(lo), "f"(hi)); return r;
}
__device__ __forceinline__ void f2unpack(ull v, float& lo, float& hi) {
    asm("mov.b64 {%0, %1}, %2;" : "=f"(lo), "=f"(hi) : "l"(v));
}

// ---------------- tables + scratch (device globals: no runtime allocation) ----
static __device__ float g_srm0[32];
static __device__ float g_refc1[32];
static __device__ float g_refc2[32];

static __device__ float g_psp0 [(size_t)NBATCH * 2  * HH * WW * TT]; //  16 MB
static __device__ float g_psps1[(size_t)NBATCH * 16 * HH * WW * TT]; // 128 MB
static __device__ float g_p2   [(size_t)NBATCH * 16 * HH * WW * TT]; // 128 MB

#define Q1F  0.60653065971263342f  /* exp(-1/2)  */
#define Q2F  0.77880078307140487f  /* exp(-1/4)  */
#define CS1F 1.3591409142295226f   /* e/2 : srm1[k] = CS1*k*Q1^k */
#define CS2F 0.67957045711476131f  /* e/4 : srm2[k] = CS2*k*Q2^k */

// ---------------- init: alpha-kernel tables (match reference truncation) -----
__global__ void k_init() {
    int t = threadIdx.x;
    if (t < 32) {
        double td = (double)t;
        double v0 = td * exp(1.0 - td);                      // srm0 (tau=1), trunc@18
        g_srm0[t]  = (t < 18) ? (float)v0 : 0.0f;
        double r1 = -3.0 * td * exp(1.0 - td);               // refk layer1, trunc@19
        g_refc1[t] = (t < 19) ? (float)r1 : 0.0f;
        double r2 = -5.0 * (td * 0.5) * exp(1.0 - td * 0.5); // refk layer2, full 32
        g_refc2[t] = (float)r2;
    }
}

// ---------------- psp0: temporal filter of binary input ---------------------
__global__ void __launch_bounds__(256) k_psp0(const float* __restrict__ in) {
    int gid = blockIdx.x * blockDim.x + threadIdx.x;   // (n,c,h,w) : 131072
    const float4* src = (const float4*)(in + (size_t)gid * TT);
    float x[TT];
#pragma unroll
    for (int v = 0; v < 8; v++) {
        float4 f = src[v];
        x[4*v] = f.x; x[4*v+1] = f.y; x[4*v+2] = f.z; x[4*v+3] = f.w;
    }
    float s0[18];
#pragma unroll
    for (int k = 0; k < 18; k++) s0[k] = g_srm0[k];
    float y[TT];
#pragma unroll
    for (int t = 0; t < TT; t++) {
        float a = 0.f;
#pragma unroll
        for (int k = 1; k < 18; k++)
            if (k <= t) a += x[t - k] * s0[k];
        y[t] = a;
    }
    float4* dst = (float4*)(g_psp0 + (size_t)gid * TT);
#pragma unroll
    for (int v = 0; v < 8; v++)
        dst[v] = make_float4(y[4*v], y[4*v+1], y[4*v+2], y[4*v+3]);
}

// ---------------- fused: conv1 (3x3, 2->16) + spike1 + psp(s1,srm1) ---------
__global__ void __launch_bounds__(256) k_l1(const float* __restrict__ w1) {
    int gid = blockIdx.x * 256 + threadIdx.x;          // (n,co,h,w) : 2^20
    int w  = gid & 127;
    int h  = (gid >> 7) & 127;
    int co = (gid >> 14) & 15;
    int n  = gid >> 18;

    float wv[18];
#pragma unroll
    for (int i = 0; i < 18; i++) wv[i] = w1[co * 18 + i];

    ull acc2[16];
#pragma unroll
    for (int i = 0; i < 16; i++) acc2[i] = 0ull;

#pragma unroll
    for (int ci = 0; ci < 2; ci++)
#pragma unroll
        for (int ky = 0; ky < 3; ky++) {
            int ih = h + ky - 1;
            if ((unsigned)ih >= 128u) continue;
#pragma unroll
            for (int kx = 0; kx < 3; kx++) {
                int iw = w + kx - 1;
                if ((unsigned)iw >= 128u) continue;
                ull wp = f2pack(wv[ci * 9 + ky * 3 + kx], wv[ci * 9 + ky * 3 + kx]);
                const ulonglong2* p = (const ulonglong2*)(g_psp0 +
                    ((((size_t)n * 2 + ci) * 128 + ih) * 128 + iw) * TT);
#pragma unroll
                for (int v = 0; v < 8; v++) {
                    ulonglong2 f = p[v];
                    acc2[2*v]   = f2fma(f.x, wp, acc2[2*v]);
                    acc2[2*v+1] = f2fma(f.y, wp, acc2[2*v+1]);
                }
            }
        }

    float acc[TT];
#pragma unroll
    for (int v = 0; v < 16; v++) f2unpack(acc2[v], acc[2*v], acc[2*v+1]);

    // spike1 (theta=3, truncated refractory len 19, exact replay) + psp1 recurrence
    float rc[19];
#pragma unroll
    for (int d = 1; d < 19; d++) rc[d] = g_refc1[d];
    float r[TT];
#pragma unroll
    for (int t = 0; t < TT; t++) r[t] = 0.f;
    float A = 0.f, B = 0.f;
#pragma unroll
    for (int t = 0; t < TT; t++) {
        float u = acc[t] + r[t];
        bool sp = (u >= 3.0f);
        B = Q1F * (B + A);
        A = Q1F * A + (sp ? 1.0f : 0.0f);
        acc[t] = CS1F * B;                 // psp(s1) output, slot t consumed
        if (sp) {
#pragma unroll
            for (int d = 1; d < 19; d++)
                if (t + d < TT) r[t + d] += rc[d];
        }
    }

    float4* dst = (float4*)(g_psps1 + (size_t)gid * TT);
#pragma unroll
    for (int v = 0; v < 8; v++)
        dst[v] = make_float4(acc[4*v], acc[4*v+1], acc[4*v+2], acc[4*v+3]);
}

// ---------------- conv2 (3x3, 18->16), smem tiled, f32x2 FMA-bound ----------
// block = 16x16 pixels, one (n, t-chunk of 4); thread = 1 pixel x 16co x 4t
__global__ void __launch_bounds__(256, 2) k_conv2(const float* __restrict__ w2) {
    extern __shared__ float smem[];
    float* tile = smem;                       // [18][18][18][4]  (ci, yy, xx, tt)
    ull*   wP   = (ull*)(smem + 23328);       // [162][16]  (w,w) pairs, co-contig

    int tid = threadIdx.x;
    int x = tid & 15, y = tid >> 4;
    int w0 = blockIdx.x * 16, h0 = blockIdx.y * 16;
    int bz = blockIdx.z;
    int n = bz >> 3, t0 = (bz & 7) * 4;

    for (int i = tid; i < 2592; i += 256) {   // w2: [co][ci][ky][kx]
        int co = i & 15, tap = i >> 4;        // wP[tap*16+co] == wP[i]
        float wgt = w2[co * 162 + tap];
        wP[i] = f2pack(wgt, wgt);
    }
    for (int i = tid; i < 5832; i += 256) {   // 18*18*18 float4 chunks
        int ci  = i / 324;
        int rem = i - ci * 324;
        int yy = rem / 18, xx = rem - yy * 18;
        int gh = h0 + yy - 1, gw = w0 + xx - 1;
        float4 v = make_float4(0.f, 0.f, 0.f, 0.f);
        if ((unsigned)gh < 128u && (unsigned)gw < 128u) {
            const float* srcp = (ci < 16)
                ? (g_psps1 + ((((size_t)n * 16 + ci)        * 128 + gh) * 128 + gw) * TT + t0)
                : (g_psp0  + ((((size_t)n * 2  + (ci - 16)) * 128 + gh) * 128 + gw) * TT + t0);
            v = *(const float4*)srcp;
        }
        *(float4*)&tile[(size_t)i * 4] = v;
    }
    __syncthreads();

    ull acc2[32];                              // [co-pair cp][4]: co=2cp:(t01,t23), co=2cp+1:(t01,t23)
#pragma unroll
    for (int i = 0; i < 32; i++) acc2[i] = 0ull;

    for (int ci = 0; ci < 18; ci++) {
#pragma unroll
        for (int ky = 0; ky < 3; ky++)
#pragma unroll
            for (int kx = 0; kx < 3; kx++) {
                ulonglong2 in2 = *(const ulonglong2*)
                    &tile[(((ci * 18) + (y + ky)) * 18 + (x + kx)) * 4];
                int tap = ci * 9 + ky * 3 + kx;
#pragma unroll
                for (int cp = 0; cp < 8; cp++) {
                    ulonglong2 wv = *(const ulonglong2*)&wP[tap * 16 + cp * 2];
                    acc2[cp*4+0] = f2fma(in2.x, wv.x, acc2[cp*4+0]);
                    acc2[cp*4+1] = f2fma(in2.y, wv.x, acc2[cp*4+1]);
                    acc2[cp*4+2] = f2fma(in2.x, wv.y, acc2[cp*4+2]);
                    acc2[cp*4+3] = f2fma(in2.y, wv.y, acc2[cp*4+3]);
                }
            }
    }

    int gh = h0 + y, gw = w0 + x;
#pragma unroll
    for (int cp = 0; cp < 8; cp++) {
#pragma unroll
        for (int s = 0; s < 2; s++) {
            int co = cp * 2 + s;
            size_t o = ((((size_t)n * 16 + co) * 128 + gh) * 128 + gw) * TT + t0;
            *(ulonglong2*)&g_p2[o] = make_ulonglong2(acc2[cp*4 + 2*s], acc2[cp*4 + 2*s + 1]);
        }
    }
}

// ---------------- fused: spike2 (theta=5) + psp(s2,srm2) + conv3 (1x1) ------
// block = 16 pixels (one row segment); phase1: (pixel,ci) spike series -> smem
// phase2: (pixel, cohalf, t-chunk) f32x2 1x1 conv, direct store to out.
#define SM_STRIDE 36
__global__ void __launch_bounds__(256, 2) k_l3(const float* __restrict__ w3,
                                               float* __restrict__ out) {
    __shared__ float sm_in[18 * 16 * SM_STRIDE];   // [ci][p][t], padded stride
    __shared__ ull   wS[18 * 32];                  // [ci][co] (w,w) pairs

    int tid = threadIdx.x;
    int n = blockIdx.z, h = blockIdx.y, w0 = blockIdx.x * 16;

    for (int i = tid; i < 576; i += 256) {         // w3: [co][ci]
        int co = i & 31, ci = i >> 5;
        float wgt = w3[co * 18 + ci];
        wS[i] = f2pack(wgt, wgt);                  // wS[ci*32+co]
    }

    // ---- phase 1: spike2 + psp(s2) per (pixel, channel) ----
    {
        int p  = tid & 15;
        int ci = tid >> 4;
        const float4* src = (const float4*)(g_p2 +
            ((((size_t)n * 16 + ci) * 128 + h) * 128 + (w0 + p)) * TT);
        float pv[TT];
#pragma unroll
        for (int v = 0; v < 8; v++) {
            float4 f = src[v];
            pv[4*v] = f.x; pv[4*v+1] = f.y; pv[4*v+2] = f.z; pv[4*v+3] = f.w;
        }
        float rc[32];
#pragma unroll
        for (int d = 1; d < 32; d++) rc[d] = g_refc2[d];
        float r[TT];
#pragma unroll
        for (int t = 0; t < TT; t++) r[t] = 0.f;
        float A = 0.f, B = 0.f;
#pragma unroll
        for (int t = 0; t < TT; t++) {
            float u = pv[t] + r[t];
            bool sp = (u >= 5.0f);
            B = Q2F * (B + A);
            A = Q2F * A + (sp ? 1.0f : 0.0f);
            pv[t] = CS2F * B;                  // psp(s2)
            if (sp) {
#pragma unroll
                for (int d = 1; d < 32; d++)
                    if (t + d < TT) r[t + d] += rc[d];
            }
        }
        float* drow = &sm_in[(ci * 16 + p) * SM_STRIDE];
#pragma unroll
        for (int v = 0; v < 8; v++)
            *(float4*)&drow[4*v] = make_float4(pv[4*v], pv[4*v+1], pv[4*v+2], pv[4*v+3]);

        if (tid < 32) {                        // psp0 channels 16,17
            int pp = tid & 15, c = tid >> 4;
            const float4* s2 = (const float4*)(g_psp0 +
                (((size_t)n * 2 + c) * 16384 + h * 128 + (w0 + pp)) * TT);
            float* dr = &sm_in[((16 + c) * 16 + pp) * SM_STRIDE];
#pragma unroll
            for (int v = 0; v < 8; v++) *(float4*)&dr[4*v] = s2[v];
        }
    }
    __syncthreads();

    // ---- phase 2: 1x1 conv (18 -> 32), f32x2 ----
    int p  = tid >> 4;
    int q  = tid & 15;
    int cohalf = q >> 3;
    int t0 = (q & 7) * 4;

    ull acc2[32];
#pragma unroll
    for (int i = 0; i < 32; i++) acc2[i] = 0ull;

#pragma unroll
    for (int ci = 0; ci < 18; ci++) {
        ulonglong2 in2 = *(const ulonglong2*)&sm_in[(ci * 16 + p) * SM_STRIDE + t0];
#pragma unroll
        for (int cp = 0; cp < 8; cp++) {
            ulonglong2 wv = *(const ulonglong2*)&wS[ci * 32 + cohalf * 16 + cp * 2];
            acc2[cp*4+0] = f2fma(in2.x, wv.x, acc2[cp*4+0]);
            acc2[cp*4+1] = f2fma(in2.y, wv.x, acc2[cp*4+1]);
            acc2[cp*4+2] = f2fma(in2.x, wv.y, acc2[cp*4+2]);
            acc2[cp*4+3] = f2fma(in2.y, wv.y, acc2[cp*4+3]);
        }
    }

    int hw = h * 128 + w0 + p;
#pragma unroll
    for (int cp = 0; cp < 8; cp++) {
#pragma unroll
        for (int s = 0; s < 2; s++) {
            int co = cohalf * 16 + cp * 2 + s;
            size_t o = (((size_t)n * 32 + co) * 16384 + hw) * TT + t0;
            *(ulonglong2*)(out + o) = make_ulonglong2(acc2[cp*4 + 2*s], acc2[cp*4 + 2*s + 1]);
        }
    }
}

// ---------------- launcher ---------------------------------------------------
extern "C" void kernel_launch(void* const* d_in, const int* in_sizes, int n_in,
                              void* d_out, int out_size) {
    const float* spikeIn = (const float*)d_in[0];
    const float* w1 = (const float*)d_in[1];
    const float* w2 = (const float*)d_in[2];
    const float* w3 = (const float*)d_in[3];
    float* out = (float*)d_out;

    const int conv2_smem = 23328 * 4 + 2592 * 8;   // 114,048 B
    cudaFuncSetAttribute(k_conv2, cudaFuncAttributeMaxDynamicSharedMemorySize, conv2_smem);

    k_init<<<1, 32>>>();
    k_psp0<<<512, 256>>>(spikeIn);
    k_l1<<<4096, 256>>>(w1);
    dim3 g2(8, 8, 32);
    k_conv2<<<g2, 256, conv2_smem>>>(w2);
    dim3 g3(8, 128, 4);
    k_l3<<<g3, 256>>>(w3, out);
}